// round 1
// baseline (speedup 1.0000x reference)
#include <cuda_runtime.h>

#define Nn 4096
#define DI 512
#define DO 128
#define NH 4
#define BM 64
#define BK 32

// ---------------- device scratch (no allocation allowed) ----------------
__device__ float g_h[Nn * DO];                       // h = x @ W
__device__ float g_el[NH * Nn], g_p[NH * Nn], g_p2[NH * Nn];  // i-side: el, exp(el), exp(0.2 el)
__device__ float g_er[NH * Nn], g_q[NH * Nn], g_q2[NH * Nn];  // j-side: er, exp(er), exp(0.2 er)

// ---------------- packed f32x2 helpers (FFMA2: 2x fp32 throughput) ------
__device__ __forceinline__ unsigned long long pack_ff(float x, float y) {
    unsigned long long r;
    asm("mov.b64 %0, {%1, %2};" : "=l"(r) : "f"(x), "f"(y));
    return r;
}
__device__ __forceinline__ void ffma2(unsigned long long &c, unsigned long long a, unsigned long long b) {
    asm("fma.rn.f32x2 %0, %1, %2, %0;" : "+l"(c) : "l"(a), "l"(b));
}
union U2 { unsigned long long u; float2 f; };

// ======================================================================
// Kernel 1: h = x @ W        [4096,512] @ [512,128] -> [4096,128] fp32
// 256 CTAs x 128 threads, BM=16 rows per CTA, f32x2 inner loop.
// ======================================================================
__global__ __launch_bounds__(128) void k_hgemm(const float* __restrict__ x,
                                               const float* __restrict__ W) {
    __shared__ float x_s[16][33];
    __shared__ __align__(16) float W_s[32][DO];

    int t  = threadIdx.x;
    int i0 = blockIdx.x * 16;
    int tx = t & 15, ty = t >> 4;   // 16 x 8 threads; each: 2 rows x 8 cols

    unsigned long long acc[2][4];
#pragma unroll
    for (int r = 0; r < 2; r++)
#pragma unroll
        for (int c = 0; c < 4; c++) acc[r][c] = 0ULL;

    for (int k0 = 0; k0 < DI; k0 += 32) {
        __syncthreads();
        {   // x tile: 16 rows x 32 k
            int i = t >> 3, kq = (t & 7) * 4;
            float4 v = *reinterpret_cast<const float4*>(&x[(i0 + i) * DI + k0 + kq]);
            x_s[i][kq]     = v.x;
            x_s[i][kq + 1] = v.y;
            x_s[i][kq + 2] = v.z;
            x_s[i][kq + 3] = v.w;
            // W tile: rows k0..k0+31 are contiguous (row-major) -> flat copy
            const float4* src = reinterpret_cast<const float4*>(W + k0 * DO);
            float4* dst = reinterpret_cast<float4*>(&W_s[0][0]);
#pragma unroll
            for (int r = 0; r < 8; r++) dst[t + 128 * r] = src[t + 128 * r];
        }
        __syncthreads();
#pragma unroll 8
        for (int k = 0; k < 32; k++) {
            ulonglong2 wv0 = *reinterpret_cast<const ulonglong2*>(&W_s[k][tx * 8]);
            ulonglong2 wv1 = *reinterpret_cast<const ulonglong2*>(&W_s[k][tx * 8 + 4]);
#pragma unroll
            for (int r = 0; r < 2; r++) {
                float xv = x_s[ty * 2 + r][k];
                unsigned long long xp = pack_ff(xv, xv);
                ffma2(acc[r][0], xp, wv0.x);
                ffma2(acc[r][1], xp, wv0.y);
                ffma2(acc[r][2], xp, wv1.x);
                ffma2(acc[r][3], xp, wv1.y);
            }
        }
    }
#pragma unroll
    for (int r = 0; r < 2; r++) {
        int row = i0 + ty * 2 + r;
        ulonglong2 o0; o0.x = acc[r][0]; o0.y = acc[r][1];
        ulonglong2 o1; o1.x = acc[r][2]; o1.y = acc[r][3];
        *reinterpret_cast<ulonglong2*>(&g_h[row * DO + tx * 8])     = o0;
        *reinterpret_cast<ulonglong2*>(&g_h[row * DO + tx * 8 + 4]) = o1;
    }
}

// ======================================================================
// Kernel 2: per-node, per-head attention projections + factorized exps.
//   el = h[n]·attn_l[h], er = h[n]·attn_r[h]
//   p=exp(el), p2=exp(0.2 el), q=exp(er), q2=exp(0.2 er)
// One warp per node.
// ======================================================================
__global__ __launch_bounds__(256) void k_node(const float* __restrict__ al,
                                              const float* __restrict__ ar) {
    int warp = threadIdx.x >> 5, lane = threadIdx.x & 31;
    int node = blockIdx.x * 8 + warp;
    float h0 = g_h[node * DO + lane];
    float h1 = g_h[node * DO + lane + 32];
    float h2 = g_h[node * DO + lane + 64];
    float h3 = g_h[node * DO + lane + 96];
#pragma unroll
    for (int hd = 0; hd < NH; hd++) {
        const float* wl = al + hd * DO;
        const float* wr = ar + hd * DO;
        float sl = h0 * wl[lane] + h1 * wl[lane + 32] + h2 * wl[lane + 64] + h3 * wl[lane + 96];
        float sr = h0 * wr[lane] + h1 * wr[lane + 32] + h2 * wr[lane + 64] + h3 * wr[lane + 96];
#pragma unroll
        for (int off = 16; off; off >>= 1) {
            sl += __shfl_xor_sync(0xffffffffu, sl, off);
            sr += __shfl_xor_sync(0xffffffffu, sr, off);
        }
        if (lane == 0) {
            int idx = hd * Nn + node;
            g_el[idx] = sl;
            g_p[idx]  = expf(sl);
            g_p2[idx] = expf(0.2f * sl);
            g_er[idx] = sr;
            g_q[idx]  = expf(sr);
            g_q2[idx] = expf(0.2f * sr);
        }
    }
}

// ======================================================================
// Kernel 3: fused masked-attention GEMM.
//   w[i,j] = adj[i,j] * ( (el_i+er_j>=0) ? p_i*q_j : p2_i*q2_j )
//   out[i,hd,:] = (sum_j w[i,j] * h[j,:]) / max(sum_j w[i,j], 1e-12) + b
// Grid: (head, i-block). BM=64 rows, all 128 d-cols, K over j in BK=32.
// Weights stored in smem pre-duplicated {w,w} so FMA loop is pure
// LDS.64/LDS.128 + FFMA2 (no pack movs).
// ======================================================================
__global__ __launch_bounds__(256, 2) void k_fused(const float* __restrict__ adj,
                                                  const float* __restrict__ bias,
                                                  float* __restrict__ out) {
    __shared__ __align__(16) float h_s[BK][DO];   // 16 KB
    __shared__ float2 w_s[BM][BK + 1];            // 16.9 KB, padded vs bank conflicts
    __shared__ float rowsum_s[BM];

    int head = blockIdx.x;
    int i0   = blockIdx.y * BM;
    int t    = threadIdx.x;
    int lane = t & 31, warp = t >> 5;
    int tx   = t & 15, ty = t >> 4;      // output micro-tile: 4 rows x 8 cols
    int rowbase = warp * 8;              // weight-compute rows for this warp

    // Hoist per-row i-side factors into registers (constant over K loop)
    float eli[8], pi[8], p2i[8];
#pragma unroll
    for (int r = 0; r < 8; r++) {
        int idx = head * Nn + i0 + rowbase + r;
        eli[r] = g_el[idx];
        pi[r]  = g_p[idx];
        p2i[r] = g_p2[idx];
    }

    unsigned long long acc[4][4];
#pragma unroll
    for (int r = 0; r < 4; r++)
#pragma unroll
        for (int c = 0; c < 4; c++) acc[r][c] = 0ULL;
    float rsum[8];
#pragma unroll
    for (int r = 0; r < 8; r++) rsum[r] = 0.0f;

    for (int k0 = 0; k0 < Nn; k0 += BK) {
        __syncthreads();
        {   // h tile: rows k0..k0+31 contiguous -> flat float4 copy (4096 floats)
            const float4* src = reinterpret_cast<const float4*>(g_h + k0 * DO);
            float4* dst = reinterpret_cast<float4*>(&h_s[0][0]);
            dst[t]       = src[t];
            dst[t + 256] = src[t + 256];
            dst[t + 512] = src[t + 512];
            dst[t + 768] = src[t + 768];
        }
        {   // weight tile: warp handles 8 rows, lane = j within tile
            int jidx = head * Nn + k0 + lane;
            float erj = g_er[jidx];
            float qj  = g_q[jidx];
            float q2j = g_q2[jidx];
            const float* ap = adj + (i0 + rowbase) * Nn + k0 + lane;
#pragma unroll
            for (int r = 0; r < 8; r++) {
                float a = ap[r * Nn];                     // coalesced 128B per row
                float s = eli[r] + erj;
                float w = (s >= 0.0f) ? (pi[r] * qj) : (p2i[r] * q2j);
                w *= a;
                w_s[rowbase + r][lane] = make_float2(w, w);  // pre-duplicated for f32x2
                rsum[r] += w;
            }
        }
        __syncthreads();
#pragma unroll 8
        for (int j = 0; j < BK; j++) {
            ulonglong2 hv0 = *reinterpret_cast<const ulonglong2*>(&h_s[j][tx * 8]);
            ulonglong2 hv1 = *reinterpret_cast<const ulonglong2*>(&h_s[j][tx * 8 + 4]);
#pragma unroll
            for (int r = 0; r < 4; r++) {
                unsigned long long wp =
                    *reinterpret_cast<const unsigned long long*>(&w_s[ty * 4 + r][j]);
                ffma2(acc[r][0], wp, hv0.x);
                ffma2(acc[r][1], wp, hv0.y);
                ffma2(acc[r][2], wp, hv1.x);
                ffma2(acc[r][3], wp, hv1.y);
            }
        }
    }

    // Row-sum (L1 norm) reduce across lanes (j)
#pragma unroll
    for (int r = 0; r < 8; r++) {
        float v = rsum[r];
#pragma unroll
        for (int off = 16; off; off >>= 1) v += __shfl_xor_sync(0xffffffffu, v, off);
        if (lane == 0) rowsum_s[rowbase + r] = v;
    }
    __syncthreads();

    float4 b0 = *reinterpret_cast<const float4*>(&bias[tx * 8]);
    float4 b1 = *reinterpret_cast<const float4*>(&bias[tx * 8 + 4]);
#pragma unroll
    for (int r = 0; r < 4; r++) {
        int row = ty * 4 + r;
        float inv = 1.0f / fmaxf(rowsum_s[row], 1e-12f);
        U2 a0, a1, a2, a3;
        a0.u = acc[r][0]; a1.u = acc[r][1]; a2.u = acc[r][2]; a3.u = acc[r][3];
        float4 o0 = make_float4(a0.f.x * inv + b0.x, a0.f.y * inv + b0.y,
                                a1.f.x * inv + b0.z, a1.f.y * inv + b0.w);
        float4 o1 = make_float4(a2.f.x * inv + b1.x, a2.f.y * inv + b1.y,
                                a3.f.x * inv + b1.z, a3.f.y * inv + b1.w);
        float* op = out + (size_t)(i0 + row) * (NH * DO) + head * DO + tx * 8;
        *reinterpret_cast<float4*>(op)     = o0;
        *reinterpret_cast<float4*>(op + 4) = o1;
    }
}

// ======================================================================
extern "C" void kernel_launch(void* const* d_in, const int* in_sizes, int n_in,
                              void* d_out, int out_size) {
    const float* adj = (const float*)d_in[0];
    const float* x   = (const float*)d_in[1];
    const float* W   = (const float*)d_in[2];
    const float* al  = (const float*)d_in[3];
    const float* ar  = (const float*)d_in[4];
    const float* b   = (const float*)d_in[5];
    float* out = (float*)d_out;

    k_hgemm<<<Nn / 16, 128>>>(x, W);
    k_node<<<Nn / 8, 256>>>(al, ar);
    k_fused<<<dim3(NH, Nn / BM), 256>>>(adj, b, out);
}

// round 3
// speedup vs baseline: 3.2099x; 3.2099x over previous
#include <cuda_runtime.h>
#include <cstdint>

#define Nn 4096
#define DI 512
#define DO 128
#define NH 4
#define BM 128
#define BK 32
#define BSTR 36          // padded row stride (floats) for fused smem tiles
#define XSTR 516         // padded row stride (floats) for hgemm x tile

// ---------------- device scratch ----------------
__device__ float g_h[Nn * DO];     // h fp32 row-major (for k_node)
__device__ float g_hT[DO * Nn];    // h tf32-rounded, transposed [d][node]
__device__ float g_el[NH * Nn], g_p[NH * Nn], g_p2[NH * Nn];
__device__ float g_er[NH * Nn], g_q[NH * Nn], g_q2[NH * Nn];

// ---------------- helpers ----------------
__device__ __forceinline__ uint32_t cvt_tf32(float x) {
    uint32_t r;
    asm("cvt.rna.tf32.f32 %0, %1;" : "=r"(r) : "f"(x));
    return r;
}
__device__ __forceinline__ void mma_tf32(float& c0, float& c1, float& c2, float& c3,
                                         uint32_t a0, uint32_t a1, uint32_t a2, uint32_t a3,
                                         uint32_t b0, uint32_t b1) {
    asm volatile("mma.sync.aligned.m16n8k8.row.col.f32.tf32.tf32.f32 "
                 "{%0,%1,%2,%3}, {%4,%5,%6,%7}, {%8,%9}, {%0,%1,%2,%3};"
                 : "+f"(c0), "+f"(c1), "+f"(c2), "+f"(c3)
                 : "r"(a0), "r"(a1), "r"(a2), "r"(a3), "r"(b0), "r"(b1));
}
__device__ __forceinline__ void lds64(uint32_t& x, uint32_t& y, const float* p) {
    asm volatile("ld.shared.v2.b32 {%0,%1}, [%2];" : "=r"(x), "=r"(y) : "l"(__cvta_generic_to_shared(p)));
}
__device__ __forceinline__ void sts64(float* p, uint32_t x, uint32_t y) {
    asm volatile("st.shared.v2.b32 [%0], {%1,%2};" :: "l"(__cvta_generic_to_shared(p)), "r"(x), "r"(y));
}
// pair-permutation: value at logical col j lives at col' so (j, j+4) are adjacent
__device__ __forceinline__ int posk(int j) {
    return (j & 24) + ((j & 3) << 1) + ((j >> 2) & 1);
}

// ======================================================================
// Kernel 1: h = x @ W via mma.sync tf32.
// CTA: 16 rows, 256 thr (8 warps). warp_n = warp&3 (32 cols), warp_k = warp>>2
// (256-deep K half). Cross-half reduce via smem. Writes g_h (fp32) and
// g_hT (tf32-rounded, transposed).
// ======================================================================
__global__ __launch_bounds__(256) void k_hgemm(const float* __restrict__ x,
                                               const float* __restrict__ W) {
    __shared__ float xs[16 * XSTR];      // pair-permuted tf32 x tile [16][512]
    __shared__ float res_s[16 * DO];     // cross-K-half partials

    int t = threadIdx.x, lane = t & 31, warp = t >> 5;
    int g = lane >> 2, ctg = lane & 3;
    int i0 = blockIdx.x * 16;
    int n0 = (warp & 3) * 32;
    int kbase = (warp >> 2) * 256;

    // stage x tile: (row, 8-col chunk) pairs; 16*64 = 1024 work items
#pragma unroll
    for (int rr = 0; rr < 4; rr++) {
        int idx = rr * 256 + t;
        int row = idx >> 6, ch = idx & 63;
        const float4* src = reinterpret_cast<const float4*>(&x[(size_t)(i0 + row) * DI + ch * 8]);
        float4 v0 = src[0], v1 = src[1];
        float* dst = &xs[row * XSTR + ch * 8];
        sts64(dst + 0, cvt_tf32(v0.x), cvt_tf32(v1.x));
        sts64(dst + 2, cvt_tf32(v0.y), cvt_tf32(v1.y));
        sts64(dst + 4, cvt_tf32(v0.z), cvt_tf32(v1.z));
        sts64(dst + 6, cvt_tf32(v0.w), cvt_tf32(v1.w));
    }
    __syncthreads();

    float acc[4][4];
#pragma unroll
    for (int nt = 0; nt < 4; nt++)
#pragma unroll
        for (int c = 0; c < 4; c++) acc[nt][c] = 0.0f;

#pragma unroll 4
    for (int kk = 0; kk < 32; kk++) {
        int k = kbase + kk * 8;
        uint32_t a0, a2, a1, a3;
        lds64(a0, a2, &xs[g * XSTR + k + ctg * 2]);
        lds64(a1, a3, &xs[(g + 8) * XSTR + k + ctg * 2]);
#pragma unroll
        for (int nt = 0; nt < 4; nt++) {
            int n = n0 + nt * 8 + g;
            uint32_t b0 = cvt_tf32(W[(size_t)(k + ctg) * DO + n]);
            uint32_t b1 = cvt_tf32(W[(size_t)(k + ctg + 4) * DO + n]);
            mma_tf32(acc[nt][0], acc[nt][1], acc[nt][2], acc[nt][3], a0, a1, a2, a3, b0, b1);
        }
    }

    // reduce the two K halves
    if (warp >= 4) {
#pragma unroll
        for (int nt = 0; nt < 4; nt++) {
            int col = n0 + nt * 8 + ctg * 2;
            res_s[g * DO + col]           = acc[nt][0];
            res_s[g * DO + col + 1]       = acc[nt][1];
            res_s[(g + 8) * DO + col]     = acc[nt][2];
            res_s[(g + 8) * DO + col + 1] = acc[nt][3];
        }
    }
    __syncthreads();
    if (warp < 4) {
#pragma unroll
        for (int nt = 0; nt < 4; nt++) {
            int col = n0 + nt * 8 + ctg * 2;
            float v0 = acc[nt][0] + res_s[g * DO + col];
            float v1 = acc[nt][1] + res_s[g * DO + col + 1];
            float v2 = acc[nt][2] + res_s[(g + 8) * DO + col];
            float v3 = acc[nt][3] + res_s[(g + 8) * DO + col + 1];
            int rA = i0 + g, rB = i0 + g + 8;
            *reinterpret_cast<float2*>(&g_h[(size_t)rA * DO + col]) = make_float2(v0, v1);
            *reinterpret_cast<float2*>(&g_h[(size_t)rB * DO + col]) = make_float2(v2, v3);
            g_hT[(size_t)col * Nn + rA]       = __uint_as_float(cvt_tf32(v0));
            g_hT[(size_t)(col + 1) * Nn + rA] = __uint_as_float(cvt_tf32(v1));
            g_hT[(size_t)col * Nn + rB]       = __uint_as_float(cvt_tf32(v2));
            g_hT[(size_t)(col + 1) * Nn + rB] = __uint_as_float(cvt_tf32(v3));
        }
    }
}

// ======================================================================
// Kernel 2: per-node projections + factorized exps (unchanged).
// ======================================================================
__global__ __launch_bounds__(256) void k_node(const float* __restrict__ al,
                                              const float* __restrict__ ar) {
    int warp = threadIdx.x >> 5, lane = threadIdx.x & 31;
    int node = blockIdx.x * 8 + warp;
    float h0 = g_h[node * DO + lane];
    float h1 = g_h[node * DO + lane + 32];
    float h2 = g_h[node * DO + lane + 64];
    float h3 = g_h[node * DO + lane + 96];
#pragma unroll
    for (int hd = 0; hd < NH; hd++) {
        const float* wl = al + hd * DO;
        const float* wr = ar + hd * DO;
        float sl = h0 * wl[lane] + h1 * wl[lane + 32] + h2 * wl[lane + 64] + h3 * wl[lane + 96];
        float sr = h0 * wr[lane] + h1 * wr[lane + 32] + h2 * wr[lane + 64] + h3 * wr[lane + 96];
#pragma unroll
        for (int off = 16; off; off >>= 1) {
            sl += __shfl_xor_sync(0xffffffffu, sl, off);
            sr += __shfl_xor_sync(0xffffffffu, sr, off);
        }
        if (lane == 0) {
            int idx = hd * Nn + node;
            g_el[idx] = sl;
            g_p[idx]  = expf(sl);
            g_p2[idx] = expf(0.2f * sl);
            g_er[idx] = sr;
            g_q[idx]  = expf(sr);
            g_q2[idx] = expf(0.2f * sr);
        }
    }
}

// ======================================================================
// Kernel 3: fused masked-attention GEMM via mma.sync tf32.
// Grid (NH, 32). 512 thr = 16 warps in 4x4 (M x N). Per stage (BK=32):
// all warps generate the tf32 weight tile + stage h tile (pair-permuted),
// then each warp does 32 mma. Register prefetch of next-stage adj/h.
// ======================================================================
__global__ __launch_bounds__(512, 1) void k_fused(const float* __restrict__ adj,
                                                  const float* __restrict__ bias,
                                                  float* __restrict__ out) {
    __shared__ float ws[BM * BSTR];     // weight tile, pair-permuted K
    __shared__ float hs[DO * BSTR];     // h tile [d][k'], pair-permuted K
    __shared__ float rowsum_s[BM];

    int t = threadIdx.x, lane = t & 31, warp = t >> 5;
    int g = lane >> 2, ctg = lane & 3;
    int head = blockIdx.x;
    int i0   = blockIdx.y * BM;
    int rm   = (warp >> 2) * 32;        // warp M origin
    int n0   = (warp & 3) * 32;         // warp N origin

    // --- producer-role constants (rows warp + 16*i, col = lane) ---
    float eli[8], pi[8], p2i[8], rsum[8];
#pragma unroll
    for (int i = 0; i < 8; i++) {
        int idx = head * Nn + i0 + warp + 16 * i;
        eli[i] = g_el[idx]; pi[i] = g_p[idx]; p2i[i] = g_p2[idx];
        rsum[i] = 0.0f;
    }
    const float* adj_base = adj + (size_t)(i0 + warp) * Nn + lane;
    int wpos = posk(lane);
    // h staging role: thread t handles row n = t>>2, k-chunk kq = (t&3)*8
    int hn = t >> 2, hkq = (t & 3) * 8;
    const float* hT_base = g_hT + (size_t)hn * Nn + hkq;

    float acc[2][4][4];
#pragma unroll
    for (int mt = 0; mt < 2; mt++)
#pragma unroll
        for (int nt = 0; nt < 4; nt++)
#pragma unroll
            for (int c = 0; c < 4; c++) acc[mt][nt][c] = 0.0f;

    // --- prologue prefetch (stage 0) ---
    float areg[8];
    float4 hr0, hr1;
    {
#pragma unroll
        for (int i = 0; i < 8; i++) areg[i] = adj_base[(size_t)(16 * i) * Nn];
        hr0 = *reinterpret_cast<const float4*>(hT_base);
        hr1 = *reinterpret_cast<const float4*>(hT_base + 4);
    }

    const int NIT = Nn / BK;
    for (int it = 0; it < NIT; ++it) {
        // ---- produce: weight tile + h tile from prefetched regs ----
        {
            int j = it * BK + lane;
            float erj = g_er[head * Nn + j];
            float qj  = g_q[head * Nn + j];
            float q2j = g_q2[head * Nn + j];
            float pq[8], pq2[8];
#pragma unroll
            for (int i = 0; i < 8; i++) { pq[i] = pi[i] * qj; pq2[i] = p2i[i] * q2j; }
#pragma unroll
            for (int i = 0; i < 8; i++) {
                float sv = eli[i] + erj;
                float w = areg[i] * ((sv >= 0.0f) ? pq[i] : pq2[i]);
                uint32_t wt = cvt_tf32(w);
                float wf = __uint_as_float(wt);
                rsum[i] += wf;
                ws[(warp + 16 * i) * BSTR + wpos] = wf;
            }
            float* hd = &hs[hn * BSTR + hkq];
            sts64(hd + 0, __float_as_uint(hr0.x), __float_as_uint(hr1.x));
            sts64(hd + 2, __float_as_uint(hr0.y), __float_as_uint(hr1.y));
            sts64(hd + 4, __float_as_uint(hr0.z), __float_as_uint(hr1.z));
            sts64(hd + 6, __float_as_uint(hr0.w), __float_as_uint(hr1.w));
        }
        __syncthreads();

        // ---- prefetch next stage (overlaps with mma) ----
        {
            int nk0 = (it + 1 < NIT) ? (it + 1) * BK : 0;
#pragma unroll
            for (int i = 0; i < 8; i++) areg[i] = adj_base[(size_t)(16 * i) * Nn + nk0];
            hr0 = *reinterpret_cast<const float4*>(hT_base + nk0);
            hr1 = *reinterpret_cast<const float4*>(hT_base + nk0 + 4);
        }

        // ---- mma phase: 4 k-chunks x 2 m-tiles x 4 n-tiles ----
#pragma unroll
        for (int kk = 0; kk < 4; kk++) {
            uint32_t b0[4], b1[4];
#pragma unroll
            for (int nt = 0; nt < 4; nt++)
                lds64(b0[nt], b1[nt], &hs[(n0 + nt * 8 + g) * BSTR + kk * 8 + ctg * 2]);
#pragma unroll
            for (int mt = 0; mt < 2; mt++) {
                uint32_t a0, a2, a1, a3;
                lds64(a0, a2, &ws[(rm + mt * 16 + g) * BSTR + kk * 8 + ctg * 2]);
                lds64(a1, a3, &ws[(rm + mt * 16 + 8 + g) * BSTR + kk * 8 + ctg * 2]);
#pragma unroll
                for (int nt = 0; nt < 4; nt++)
                    mma_tf32(acc[mt][nt][0], acc[mt][nt][1], acc[mt][nt][2], acc[mt][nt][3],
                             a0, a1, a2, a3, b0[nt], b1[nt]);
            }
        }
        __syncthreads();
    }

    // ---- rowsum reduce across lanes (j dimension) ----
#pragma unroll
    for (int i = 0; i < 8; i++) {
        float v = rsum[i];
#pragma unroll
        for (int off = 16; off; off >>= 1) v += __shfl_xor_sync(0xffffffffu, v, off);
        if (lane == 0) rowsum_s[warp + 16 * i] = v;
    }
    __syncthreads();

    // ---- epilogue: normalize + bias + store ----
#pragma unroll
    for (int mt = 0; mt < 2; mt++) {
        int lrA = rm + mt * 16 + g;
        int lrB = lrA + 8;
        float invA = 1.0f / fmaxf(rowsum_s[lrA], 1e-12f);
        float invB = 1.0f / fmaxf(rowsum_s[lrB], 1e-12f);
#pragma unroll
        for (int nt = 0; nt < 4; nt++) {
            int bcol = n0 + nt * 8 + ctg * 2;
            float2 bv = *reinterpret_cast<const float2*>(&bias[bcol]);
            float* opA = out + (size_t)(i0 + lrA) * (NH * DO) + head * DO + bcol;
            float* opB = out + (size_t)(i0 + lrB) * (NH * DO) + head * DO + bcol;
            *reinterpret_cast<float2*>(opA) =
                make_float2(acc[mt][nt][0] * invA + bv.x, acc[mt][nt][1] * invA + bv.y);
            *reinterpret_cast<float2*>(opB) =
                make_float2(acc[mt][nt][2] * invB + bv.x, acc[mt][nt][3] * invB + bv.y);
        }
    }
}

// ======================================================================
extern "C" void kernel_launch(void* const* d_in, const int* in_sizes, int n_in,
                              void* d_out, int out_size) {
    const float* adj = (const float*)d_in[0];
    const float* x   = (const float*)d_in[1];
    const float* W   = (const float*)d_in[2];
    const float* al  = (const float*)d_in[3];
    const float* ar  = (const float*)d_in[4];
    const float* b   = (const float*)d_in[5];
    float* out = (float*)d_out;

    k_hgemm<<<Nn / 16, 256>>>(x, W);
    k_node<<<Nn / 8, 256>>>(al, ar);
    k_fused<<<dim3(NH, Nn / BM), 512>>>(adj, b, out);
}